// round 1
// baseline (speedup 1.0000x reference)
#include <cuda_runtime.h>
#include <cuda_bf16.h>
#include <cstdint>

// Problem dims (fixed per reference setup_inputs)
#define N_ROWS 8192         // rows of x
#define O_COLS 4096         // rows of W == output cols
#define K_DIM  4096         // inner dim
#define KWORDS 128          // K_DIM / 32 packed words per row

// ---- scratch in device globals (no dynamic allocation allowed) ----
__device__ unsigned xp_g[(size_t)N_ROWS * KWORDS];   // 4 MB packed sign bits of x
__device__ unsigned wp_g[(size_t)O_COLS * KWORDS];   // 2 MB packed sign bits of W
__device__ float    psum_g[N_ROWS];                  // per-row |x| partial sums
__device__ float    mean_g;                          // mean(|x|)

// ============================================================
// Pack x rows into sign bits (bit=1 iff negative) + accumulate |x|.
// One block per row, 128 threads (4 warps). Each warp packs 32 words.
// ============================================================
__global__ void pack_x_kernel(const float* __restrict__ x) {
    const int row  = blockIdx.x;
    const int tid  = threadIdx.x;
    const int lane = tid & 31;
    const int warp = tid >> 5;      // 0..3

    const float* xr = x + (size_t)row * K_DIM;
    float s = 0.f;

    #pragma unroll 4
    for (int it = 0; it < 32; it++) {
        const int w = warp * 32 + it;             // word index 0..127
        const float v = xr[w * 32 + lane];        // coalesced 128B per warp
        s += fabsf(v);
        const unsigned bits = __ballot_sync(0xffffffffu, __float_as_uint(v) >> 31);
        if (lane == 0) xp_g[(size_t)row * KWORDS + w] = bits;
    }

    // deterministic block tree reduction of |x| partials
    __shared__ float red[128];
    red[tid] = s;
    __syncthreads();
    #pragma unroll
    for (int off = 64; off > 0; off >>= 1) {
        if (tid < off) red[tid] += red[tid + off];
        __syncthreads();
    }
    if (tid == 0) psum_g[row] = red[0];
}

// ============================================================
// Pack W rows into sign bits (W is ±1 float; sign bit suffices).
// ============================================================
__global__ void pack_w_kernel(const float* __restrict__ W) {
    const int row  = blockIdx.x;
    const int tid  = threadIdx.x;
    const int lane = tid & 31;
    const int warp = tid >> 5;

    const float* wr = W + (size_t)row * K_DIM;

    #pragma unroll 4
    for (int it = 0; it < 32; it++) {
        const int w = warp * 32 + it;
        const float v = wr[w * 32 + lane];
        const unsigned bits = __ballot_sync(0xffffffffu, __float_as_uint(v) >> 31);
        if (lane == 0) wp_g[(size_t)row * KWORDS + w] = bits;
    }
}

// ============================================================
// Final deterministic reduction: mean(|x|) over 8192 row partials.
// ============================================================
__global__ void reduce_mean_kernel() {
    __shared__ float red[1024];
    const int tid = threadIdx.x;
    float s = 0.f;
    for (int i = tid; i < N_ROWS; i += 1024) s += psum_g[i];
    red[tid] = s;
    __syncthreads();
    #pragma unroll
    for (int off = 512; off > 0; off >>= 1) {
        if (tid < off) red[tid] += red[tid + off];
        __syncthreads();
    }
    if (tid == 0) mean_g = red[0] * (1.0f / ((float)N_ROWS * (float)K_DIM));
}

// ============================================================
// XNOR-popcount GEMM.
// Block: 64 (n) x 64 (o) output tile, 256 threads, 4x4 register tile each.
// K loop in chunks of 16 packed words through shared memory.
// dot(n,o) = K_DIM - 2 * popc(xbits ^ wbits)
// out = (dot + b[o]) * mean(|x|)
// ============================================================
#define BT 64      // block tile (both dims)
#define KW 16      // words per K chunk
#define KPAD 68    // padded row length (bank-conflict avoidance; 68*4B keeps 16B align)

__global__ __launch_bounds__(256, 4)
void bgemm_kernel(const float* __restrict__ b, float* __restrict__ out) {
    __shared__ __align__(16) unsigned xs[KW][KPAD];  // [kword][n-row-in-tile]
    __shared__ __align__(16) unsigned ws[KW][KPAD];  // [kword][o-row-in-tile]

    const int tid = threadIdx.x;         // 0..255
    const int tx  = tid & 15;            // o sub-tile
    const int ty  = tid >> 4;            // n sub-tile
    const int o0  = blockIdx.x * BT;
    const int n0  = blockIdx.y * BT;

    // loader mapping: each thread loads one uint4 (4 words) from one row
    const int lrow = tid >> 2;           // 0..63
    const int lq   = tid & 3;            // 0..3  (which uint4 within 16-word chunk)

    int acc[4][4];
    #pragma unroll
    for (int i = 0; i < 4; i++)
        #pragma unroll
        for (int j = 0; j < 4; j++) acc[i][j] = 0;

    for (int kw0 = 0; kw0 < KWORDS; kw0 += KW) {
        const uint4 xv = *(const uint4*)&xp_g[(size_t)(n0 + lrow) * KWORDS + kw0 + lq * 4];
        const uint4 wv = *(const uint4*)&wp_g[(size_t)(o0 + lrow) * KWORDS + kw0 + lq * 4];

        __syncthreads();   // previous chunk fully consumed
        xs[lq * 4 + 0][lrow] = xv.x;
        xs[lq * 4 + 1][lrow] = xv.y;
        xs[lq * 4 + 2][lrow] = xv.z;
        xs[lq * 4 + 3][lrow] = xv.w;
        ws[lq * 4 + 0][lrow] = wv.x;
        ws[lq * 4 + 1][lrow] = wv.y;
        ws[lq * 4 + 2][lrow] = wv.z;
        ws[lq * 4 + 3][lrow] = wv.w;
        __syncthreads();

        #pragma unroll
        for (int k = 0; k < KW; k++) {
            const uint4 a = *(const uint4*)&xs[k][ty * 4];   // broadcast across tx
            const uint4 c = *(const uint4*)&ws[k][tx * 4];   // 256B clean sweep
            acc[0][0] += __popc(a.x ^ c.x); acc[0][1] += __popc(a.x ^ c.y);
            acc[0][2] += __popc(a.x ^ c.z); acc[0][3] += __popc(a.x ^ c.w);
            acc[1][0] += __popc(a.y ^ c.x); acc[1][1] += __popc(a.y ^ c.y);
            acc[1][2] += __popc(a.y ^ c.z); acc[1][3] += __popc(a.y ^ c.w);
            acc[2][0] += __popc(a.z ^ c.x); acc[2][1] += __popc(a.z ^ c.y);
            acc[2][2] += __popc(a.z ^ c.z); acc[2][3] += __popc(a.z ^ c.w);
            acc[3][0] += __popc(a.w ^ c.x); acc[3][1] += __popc(a.w ^ c.y);
            acc[3][2] += __popc(a.w ^ c.z); acc[3][3] += __popc(a.w ^ c.w);
        }
    }

    const float mean = mean_g;
    const int o_base = o0 + tx * 4;
    const int n_base = n0 + ty * 4;
    const float4 bb = *(const float4*)&b[o_base];

    #pragma unroll
    for (int i = 0; i < 4; i++) {
        float4 r;
        r.x = ((float)(K_DIM - 2 * acc[i][0]) + bb.x) * mean;
        r.y = ((float)(K_DIM - 2 * acc[i][1]) + bb.y) * mean;
        r.z = ((float)(K_DIM - 2 * acc[i][2]) + bb.z) * mean;
        r.w = ((float)(K_DIM - 2 * acc[i][3]) + bb.w) * mean;
        *(float4*)&out[(size_t)(n_base + i) * O_COLS + o_base] = r;
    }
}

// ============================================================
// Launch: pack -> mean -> gemm (all stream-ordered, graph-capturable)
// ============================================================
extern "C" void kernel_launch(void* const* d_in, const int* in_sizes, int n_in,
                              void* d_out, int out_size) {
    const float* x = (const float*)d_in[0];   // [8192, 4096]
    const float* W = (const float*)d_in[1];   // [4096, 4096]
    const float* b = (const float*)d_in[2];   // [4096]
    float* out = (float*)d_out;               // [8192, 4096]

    pack_x_kernel<<<N_ROWS, 128>>>(x);
    pack_w_kernel<<<O_COLS, 128>>>(W);
    reduce_mean_kernel<<<1, 1024>>>();

    dim3 grid(O_COLS / BT, N_ROWS / BT);      // (64, 128)
    bgemm_kernel<<<grid, 256>>>(b, out);
}